// round 17
// baseline (speedup 1.0000x reference)
#include <cuda_runtime.h>
#include <cuda_bf16.h>
#include <cstdint>

#define MARGIN 9.0f
#define NB  32
#define NEI 100000
#define ND  64
#define TPB 256
#define EPB 256       // 2 strips of 16 entities per warp
#define QLD 72        // q row stride in words: LDS.64 banks 8g+2t, conflict-free/phase

// static smem: Q tf32 [32][72] u32, qn [32] f32  = 9344 B
#define SMEM_Q  0
#define SMEM_QN (32*QLD*4)
__shared__ __align__(16) unsigned char smem_s[32*QLD*4 + 32*4];

__device__ __forceinline__ void mma_tf32(float* c, uint32_t a0, uint32_t a1,
                                         uint32_t a2, uint32_t a3,
                                         uint32_t b0, uint32_t b1) {
    asm volatile("mma.sync.aligned.m16n8k8.row.col.f32.tf32.tf32.f32 "
                 "{%0,%1,%2,%3}, {%4,%5,%6,%7}, {%8,%9}, {%0,%1,%2,%3};"
                 : "+f"(c[0]), "+f"(c[1]), "+f"(c[2]), "+f"(c[3])
                 : "r"(a0), "r"(a1), "r"(a2), "r"(a3), "r"(b0), "r"(b1));
}
__device__ __forceinline__ uint32_t cvt_tf32(float x) {
    uint32_t r; asm("cvt.rna.tf32.f32 %0, %1;" : "=r"(r) : "f"(x)); return r;
}
__device__ __forceinline__ float sqrt_ap(float x) {
    float r; asm("sqrt.approx.f32 %0, %1;" : "=f"(r) : "f"(x)); return r;
}

__global__ void __launch_bounds__(TPB, 4) transe_kernel(
    const void* __restrict__ subp, const void* __restrict__ relp,
    const float* __restrict__ emb_e, const float* __restrict__ emb_rel,
    float* __restrict__ out)
{
    const int tid = threadIdx.x;
    const long long ebase = (long long)blockIdx.x * EPB;
    float* qn = (float*)(smem_s + SMEM_QN);
    uint32_t* qsm = (uint32_t*)(smem_s + SMEM_Q);

    const int wid = tid >> 5;
    const int ln  = tid & 31;
    const int nwarp = wid * 32;          // warp's 32-entity range (2 strips of 16)
    const int t = ln & 3;                // k-group lane
    const int g = ln >> 2;               // n-row within n8 tile

    // ---- strip-0 B prefetch (kk=0,1) issued FIRST: hides L2 latency under
    // the q gather chain + barrier. Rows clamped; clamped cols never stored.
    float2 buf[2][2];
    {
        long long n0 = ebase + nwarp + g;
        long long n1 = n0 + 8;
        if (n0 > NEI - 1) n0 = NEI - 1;
        if (n1 > NEI - 1) n1 = NEI - 1;
        const float* p0 = emb_e + n0 * ND + 2 * t;
        const float* p1 = emb_e + n1 * ND + 2 * t;
        #pragma unroll
        for (int kk = 0; kk < 2; kk++) {
            buf[kk][0] = *(const float2*)(p0 + kk*8);
            buf[kk][1] = *(const float2*)(p1 + kk*8);
        }
    }

    // ---- q fill: row = tid>>3, chunk = tid&7; fp32 sums -> tf32 to smem ----
    {
        // index dtype detection (jnp.int64 may silently be int32); 64B read safe.
        const long long* sub64 = (const long long*)subp;
        const int*       sub32 = (const int*)subp;
        const long long* rel64 = (const long long*)relp;
        const int*       rel32 = (const int*)relp;
        int row = tid >> 3;
        int ch  = tid & 7;                  // dims [ch*8, ch*8+8)
        long long s64v = sub64[row];  int s32v = sub32[row];
        long long r64v = rel64[row];  int r32v = rel32[row];
        long long dv   = sub64[ln & 7];     // first 8 words, 64B: safe both layouts
        bool ok = (dv >= 0 && dv < NEI);
        bool is64 = (__ballot_sync(0xffffffffu, ok) == 0xffffffffu);
        long long s = is64 ? s64v : (long long)s32v;
        long long r = is64 ? r64v : (long long)r32v;
        float4 e0 = ((const float4*)emb_e)[s*16 + 2*ch];
        float4 e1 = ((const float4*)emb_e)[s*16 + 2*ch + 1];
        float4 r0v = ((const float4*)emb_rel)[r*16 + 2*ch];
        float4 r1v = ((const float4*)emb_rel)[r*16 + 2*ch + 1];
        float vv[8] = {e0.x+r0v.x, e0.y+r0v.y, e0.z+r0v.z, e0.w+r0v.w,
                       e1.x+r1v.x, e1.y+r1v.y, e1.z+r1v.z, e1.w+r1v.w};
        uint32_t tv[8];
        float part = 0.f;
        #pragma unroll
        for (int j = 0; j < 8; j++) {
            tv[j] = cvt_tf32(vv[j]);
            part = fmaf(vv[j], vv[j], part);
        }
        uint32_t* dst = qsm + row * QLD + ch * 8;
        *(uint4*)(dst)     = make_uint4(tv[0], tv[1], tv[2], tv[3]);
        *(uint4*)(dst + 4) = make_uint4(tv[4], tv[5], tv[6], tv[7]);
        part += __shfl_xor_sync(0xffffffffu, part, 1);
        part += __shfl_xor_sync(0xffffffffu, part, 2);
        part += __shfl_xor_sync(0xffffffffu, part, 4);
        if (ch == 0) qn[row] = part;
    }
    __syncthreads();

    // ---- A (Q) LDS addresses: k-permuted tf32 frags, conflict-free per phase.
    // Logical cols (t, t+4) of each k8 chunk hold physical dims (2t, 2t+1), so
    // (a0,a2) = LDS.64 at Q[row][kk*8+2t], (a1,a3) = same at row+8; B matches
    // with its natural float2 (dims 2t, 2t+1). Dot is k-permutation-invariant.
    const uint32_t* qa = qsm + g * QLD + 2 * t;
    const int cb = 2 * t;

    // ---- strip loop: unroll 1 so frag/accum registers are reused ----
    #pragma unroll 1
    for (int s = 0; s < 2; s++) {
        const int nbase = nwarp + s * 16;
        long long n0 = ebase + nbase + g;
        long long n1 = n0 + 8;
        if (n0 > NEI - 1) n0 = NEI - 1;
        if (n1 > NEI - 1) n1 = NEI - 1;
        const float* pB0 = emb_e + n0 * ND + 2 * t;
        const float* pB1 = emb_e + n1 * ND + 2 * t;
        if (s > 0) {    // strip 0's kk=0,1 already in flight since kernel start
            #pragma unroll
            for (int kk = 0; kk < 2; kk++) {
                buf[kk][0] = *(const float2*)(pB0 + kk*8);
                buf[kk][1] = *(const float2*)(pB1 + kk*8);
            }
        }

        float c[2][2][4];
        #pragma unroll
        for (int mi = 0; mi < 2; mi++)
            #pragma unroll
            for (int nj = 0; nj < 2; nj++)
                #pragma unroll
                for (int j = 0; j < 4; j++) c[mi][nj][j] = 0.f;

        float en0 = 0.f, en1 = 0.f;

        #pragma unroll
        for (int kk = 0; kk < 8; kk++) {
            float2 f0 = buf[kk&1][0];
            float2 f1 = buf[kk&1][1];
            if (kk < 6) {    // ping-pong prefetch, distance 2 (R10/R11 validated)
                buf[kk&1][0] = *(const float2*)(pB0 + (kk+2)*8);
                buf[kk&1][1] = *(const float2*)(pB1 + (kk+2)*8);
            }
            uint32_t b00 = cvt_tf32(f0.x), b01 = cvt_tf32(f0.y);
            uint32_t b10 = cvt_tf32(f1.x), b11 = cvt_tf32(f1.y);
            en0 = fmaf(f0.x, f0.x, fmaf(f0.y, f0.y, en0));
            en1 = fmaf(f1.x, f1.x, fmaf(f1.y, f1.y, en1));
            const int ko = kk * 8;
            #pragma unroll
            for (int mi = 0; mi < 2; mi++) {
                uint2 p0 = *(const uint2*)(qa + (mi*16)     * QLD + ko);   // (a0,a2)
                uint2 p1 = *(const uint2*)(qa + (mi*16 + 8) * QLD + ko);   // (a1,a3)
                mma_tf32(c[mi][0], p0.x, p1.x, p0.y, p1.y, b00, b01);
                mma_tf32(c[mi][1], p0.x, p1.x, p0.y, p1.y, b10, b11);
            }
        }

        // ---- entity norms: reduce over 4-lane k-group, redistribute to col owners ----
        en0 += __shfl_xor_sync(0xffffffffu, en0, 1);
        en0 += __shfl_xor_sync(0xffffffffu, en0, 2);
        en1 += __shfl_xor_sync(0xffffffffu, en1, 1);
        en1 += __shfl_xor_sync(0xffffffffu, en1, 2);
        float enA0 = __shfl_sync(0xffffffffu, en0, 8*t);
        float enA1 = __shfl_sync(0xffffffffu, en0, 8*t + 4);
        float enB0 = __shfl_sync(0xffffffffu, en1, 8*t);
        float enB1 = __shfl_sync(0xffffffffu, en1, 8*t + 4);

        // ---- epilogue: dist^2 = qn + en - 2*dot ; out = MARGIN - sqrt(max(.,0)) ----
        #pragma unroll
        for (int mi = 0; mi < 2; mi++) {
            #pragma unroll
            for (int nj = 0; nj < 2; nj++) {
                long long eg = ebase + nbase + nj*8 + cb;
                if (eg < NEI) {   // eg even, NEI even -> pair-safe
                    float el = nj ? enB0 : enA0;
                    float eh = nj ? enB1 : enA1;
                    int row = mi*16 + g;
                    float q0 = qn[row], q1 = qn[row + 8];
                    float d0 = q0 + el - 2.f * c[mi][nj][0];
                    float d1 = q0 + eh - 2.f * c[mi][nj][1];
                    float d2 = q1 + el - 2.f * c[mi][nj][2];
                    float d3 = q1 + eh - 2.f * c[mi][nj][3];
                    float v0 = MARGIN - sqrt_ap(fmaxf(d0, 0.f));
                    float v1 = MARGIN - sqrt_ap(fmaxf(d1, 0.f));
                    float v2 = MARGIN - sqrt_ap(fmaxf(d2, 0.f));
                    float v3 = MARGIN - sqrt_ap(fmaxf(d3, 0.f));
                    *(float2*)(out + (long long)row * NEI + eg)       = make_float2(v0, v1);
                    *(float2*)(out + (long long)(row + 8) * NEI + eg) = make_float2(v2, v3);
                }
            }
        }
    }
}

extern "C" void kernel_launch(void* const* d_in, const int* in_sizes, int n_in,
                              void* d_out, int out_size) {
    (void)in_sizes; (void)n_in; (void)out_size;
    const void* sub      = d_in[0];
    const void* rel      = d_in[1];
    const float* emb_e   = (const float*)d_in[2];
    const float* emb_rel = (const float*)d_in[3];
    float* out = (float*)d_out;

    int grid = (NEI + EPB - 1) / EPB;   // 391 blocks
    transe_kernel<<<grid, TPB>>>(sub, rel, emb_e, emb_rel, out);
}